// round 13
// baseline (speedup 1.0000x reference)
#include <cuda_runtime.h>
#include <math.h>

// SLAYFeatures R13 = R12 with 4-stage in-thread pipeline over row-batches of 2:
// batch b's stores interleave into batch b+1's accumulate loop; only the last
// batch's 32 float4 stores are exposed. Keeps R5's LDG/L2 omega + reg accums.
// out[b, r*8192 + h*512 + p*32 + m] = poly[b,h,p] * prf[b,r,h,m]

#define NB 8
#define THREADS 256

__global__ __launch_bounds__(THREADS, 3) void slay_kernel(
    const float* __restrict__ x,        // [8192,1024]
    const float* __restrict__ omega,    // [2,16,64,32]
    const float* __restrict__ anchors,  // [16,64]
    float* __restrict__ out,            // [8192,16384]
    float s0, float s1, float c0, float c1, float e0, float e1)
{
    __shared__ __align__(16) float xs[NB][1024];   // normalized x rows (32 KB)
    __shared__ __align__(16) float poly[NB][256];  // [b][h*16+p]        (8 KB)

    const int t  = threadIdx.x;
    const int b0 = blockIdx.x * NB;

    // ---------- Phase 1: load x, per-head normalize ----------
    {
        float4 v[NB];
        float  ss[NB];
        const float4* x4 = (const float4*)x;
#pragma unroll
        for (int k = 0; k < NB; k++) {
            v[k] = x4[(size_t)(b0 + k) * 256 + t];
            ss[k] = v[k].x*v[k].x + v[k].y*v[k].y + v[k].z*v[k].z + v[k].w*v[k].w;
        }
#pragma unroll
        for (int k = 0; k < NB; k++) {
#pragma unroll
            for (int off = 8; off; off >>= 1)
                ss[k] += __shfl_xor_sync(0xffffffffu, ss[k], off);
            float inv = 1.0f / (sqrtf(fmaxf(ss[k], 1e-12f)) + 1e-4f);
            float4 w = v[k];
            w.x *= inv; w.y *= inv; w.z *= inv; w.w *= inv;
            ((float4*)xs[k])[t] = w;
        }
    }
    __syncthreads();

    // ---------- Phase 2: poly features. thread = (h, p) ----------
    {
        const int h = t >> 4, p = t & 15;
        float acc[NB];
#pragma unroll
        for (int k = 0; k < NB; k++) acc[k] = 0.0f;
        const float4* an = (const float4*)(anchors + p * 64);
#pragma unroll 4
        for (int d4 = 0; d4 < 16; d4++) {
            float4 a = an[d4];
#pragma unroll
            for (int k = 0; k < NB; k++) {
                float4 xv = ((const float4*)xs[k])[h * 16 + d4];
                acc[k] += xv.x*a.x + xv.y*a.y + xv.z*a.z + xv.w*a.w;
            }
        }
#pragma unroll
        for (int k = 0; k < NB; k++)
            poly[k][t] = acc[k] * acc[k] * 0.25f;   // /sqrt(P=16)
    }
    __syncthreads();

    // ---------- Phase 3: 4-stage pipelined PRF + stores ----------
    {
        const int r  = t >> 7;
        const int h  = (t >> 3) & 15;
        const int m4 = t & 7;
        const float sr = r ? s1 : s0;
        const float cr = r ? c1 : c0;
        const float er = r ? e1 : e0;
        const float4* og = (const float4*)omega + (size_t)((r * 16 + h) * 64) * 8 + m4;
        const size_t obase = r * 8192 + h * 512 + m4 * 4;

        float4 prPrev[2];

#pragma unroll
        for (int bb = 0; bb < 4; bb++) {
            const int k0 = bb * 2;          // rows of this batch
            float4 acc0 = make_float4(0.f, 0.f, 0.f, 0.f);
            float4 acc1 = make_float4(0.f, 0.f, 0.f, 0.f);

#pragma unroll
            for (int d4 = 0; d4 < 16; d4++) {
                float4 o0 = og[(4 * d4 + 0) * 8];
                float4 o1 = og[(4 * d4 + 1) * 8];
                float4 o2 = og[(4 * d4 + 2) * 8];
                float4 o3 = og[(4 * d4 + 3) * 8];

                float4 xv0 = ((const float4*)xs[k0])[h * 16 + d4];
                float4 xv1 = ((const float4*)xs[k0 + 1])[h * 16 + d4];

                acc0.x += xv0.x*o0.x; acc0.y += xv0.x*o0.y; acc0.z += xv0.x*o0.z; acc0.w += xv0.x*o0.w;
                acc0.x += xv0.y*o1.x; acc0.y += xv0.y*o1.y; acc0.z += xv0.y*o1.z; acc0.w += xv0.y*o1.w;
                acc0.x += xv0.z*o2.x; acc0.y += xv0.z*o2.y; acc0.z += xv0.z*o2.z; acc0.w += xv0.z*o2.w;
                acc0.x += xv0.w*o3.x; acc0.y += xv0.w*o3.y; acc0.z += xv0.w*o3.z; acc0.w += xv0.w*o3.w;

                acc1.x += xv1.x*o0.x; acc1.y += xv1.x*o0.y; acc1.z += xv1.x*o0.z; acc1.w += xv1.x*o0.w;
                acc1.x += xv1.y*o1.x; acc1.y += xv1.y*o1.y; acc1.z += xv1.y*o1.z; acc1.w += xv1.y*o1.w;
                acc1.x += xv1.z*o2.x; acc1.y += xv1.z*o2.y; acc1.z += xv1.z*o2.z; acc1.w += xv1.z*o2.w;
                acc1.x += xv1.w*o3.x; acc1.y += xv1.w*o3.y; acc1.z += xv1.w*o3.z; acc1.w += xv1.w*o3.w;

                if (bb > 0) {
                    // interleave 2 of previous batch's 32 stores per iteration
#pragma unroll
                    for (int j = 0; j < 2; j++) {
                        const int idx = d4 * 2 + j;       // 0..31
                        const int kr  = (bb - 1) * 2 + (idx & 1);
                        const int p   = idx >> 1;
                        const float pf = poly[kr][h * 16 + p];
                        float4 pa = prPrev[idx & 1];
                        float4 o;
                        o.x = pf * pa.x; o.y = pf * pa.y; o.z = pf * pa.z; o.w = pf * pa.w;
                        __stcs((float4*)(out + (size_t)(b0 + kr) * 16384 + obase + (size_t)p * 32), o);
                    }
                }
            }

            prPrev[0].x = er * __expf(fminf(fmaxf(acc0.x * cr - sr, -20.f), 20.f));
            prPrev[0].y = er * __expf(fminf(fmaxf(acc0.y * cr - sr, -20.f), 20.f));
            prPrev[0].z = er * __expf(fminf(fmaxf(acc0.z * cr - sr, -20.f), 20.f));
            prPrev[0].w = er * __expf(fminf(fmaxf(acc0.w * cr - sr, -20.f), 20.f));
            prPrev[1].x = er * __expf(fminf(fmaxf(acc1.x * cr - sr, -20.f), 20.f));
            prPrev[1].y = er * __expf(fminf(fmaxf(acc1.y * cr - sr, -20.f), 20.f));
            prPrev[1].z = er * __expf(fminf(fmaxf(acc1.z * cr - sr, -20.f), 20.f));
            prPrev[1].w = er * __expf(fminf(fmaxf(acc1.w * cr - sr, -20.f), 20.f));
        }

        // ---- Tail: last batch's 32 stores (rows 6,7) ----
#pragma unroll
        for (int j = 0; j < 2; j++) {
            const int kr = 6 + j;
            float* ob = out + (size_t)(b0 + kr) * 16384 + obase;
            const float* pl = &poly[kr][h * 16];
            float4 pa = prPrev[j];
#pragma unroll
            for (int p = 0; p < 16; p++) {
                const float pf = pl[p];
                float4 o;
                o.x = pf * pa.x; o.y = pf * pa.y; o.z = pf * pa.z; o.w = pf * pa.w;
                __stcs((float4*)(ob + p * 32), o);
            }
        }
    }
}

extern "C" void kernel_launch(void* const* d_in, const int* in_sizes, int n_in,
                              void* d_out, int out_size) {
    const float* x       = (const float*)d_in[0];
    const float* omega   = (const float*)d_in[1];
    const float* anchors = (const float*)d_in[2];
    float* out = (float*)d_out;

    const double C   = 2.0 + 1e-6;
    const double rt2 = 1.4142135623730951;
    const double n0d = 2.0 - rt2, n1d = 2.0 + rt2;
    const double w0d = (2.0 + rt2) / 4.0, w1d = (2.0 - rt2) / 4.0;

    float s0 = (float)(n0d / C);
    float s1 = (float)(n1d / C);
    float c0 = sqrtf(2.0f * s0);
    float c1 = sqrtf(2.0f * s1);
    float invSqrtM = 1.0f / sqrtf(32.0f);
    float e0 = sqrtf((float)(w0d / C)) * invSqrtM;
    float e1 = sqrtf((float)(w1d / C)) * invSqrtM;

    slay_kernel<<<8192 / NB, THREADS>>>(x, omega, anchors, out,
                                        s0, s1, c0, c1, e0, e1);
    (void)in_sizes; (void)n_in; (void)out_size;
}

// round 14
// speedup vs baseline: 3.0680x; 3.0680x over previous
#include <cuda_runtime.h>
#include <math.h>

// SLAYFeatures R14 = R12 (batch-split phase 3, interleaved 512B store bursts)
//  + anchors staged TRANSPOSED in smem: kills the 16-way divergent anchor LDGs
//    in phase 2 (was ~1/3 of L1 wavefronts, and an L2 request storm).
// out[b, r*8192 + h*512 + p*32 + m] = poly[b,h,p] * prf[b,r,h,m]

#define NB 8
#define THREADS 256

__global__ __launch_bounds__(THREADS, 3) void slay_kernel(
    const float* __restrict__ x,        // [8192,1024]
    const float* __restrict__ omega,    // [2,16,64,32]
    const float* __restrict__ anchors,  // [16,64]
    float* __restrict__ out,            // [8192,16384]
    float s0, float s1, float c0, float c1, float e0, float e1)
{
    __shared__ __align__(16) float xs[NB][1024];   // normalized x rows (32 KB)
    __shared__ __align__(16) float poly[NB][256];  // [b][h*16+p]        (8 KB)
    __shared__ float an_t[64][17];                 // anchors^T, padded  (4.25 KB)

    const int t  = threadIdx.x;
    const int b0 = blockIdx.x * NB;

    // ---------- Phase 0: stage anchors transposed (one-time, coalesced reads) ----------
    {
#pragma unroll
        for (int i = 0; i < 4; i++) {
            int idx = i * 256 + t;          // 0..1023 over anchors[p][d]
            int p = idx >> 6;
            int d = idx & 63;
            an_t[d][p] = anchors[idx];
        }
    }

    // ---------- Phase 1: load x, per-head normalize ----------
    {
        float4 v[NB];
        float  ss[NB];
        const float4* x4 = (const float4*)x;
#pragma unroll
        for (int k = 0; k < NB; k++) {
            v[k] = x4[(size_t)(b0 + k) * 256 + t];
            ss[k] = v[k].x*v[k].x + v[k].y*v[k].y + v[k].z*v[k].z + v[k].w*v[k].w;
        }
#pragma unroll
        for (int k = 0; k < NB; k++) {
#pragma unroll
            for (int off = 8; off; off >>= 1)
                ss[k] += __shfl_xor_sync(0xffffffffu, ss[k], off);
            float inv = 1.0f / (sqrtf(fmaxf(ss[k], 1e-12f)) + 1e-4f);
            float4 w = v[k];
            w.x *= inv; w.y *= inv; w.z *= inv; w.w *= inv;
            ((float4*)xs[k])[t] = w;
        }
    }
    __syncthreads();

    // ---------- Phase 2: poly features. thread = (h, p); anchors from smem ----------
    {
        const int h = t >> 4, p = t & 15;
        float acc[NB];
#pragma unroll
        for (int k = 0; k < NB; k++) acc[k] = 0.0f;
#pragma unroll 4
        for (int d4 = 0; d4 < 16; d4++) {
            float ax = an_t[d4 * 4 + 0][p];
            float ay = an_t[d4 * 4 + 1][p];
            float az = an_t[d4 * 4 + 2][p];
            float aw = an_t[d4 * 4 + 3][p];
#pragma unroll
            for (int k = 0; k < NB; k++) {
                float4 xv = ((const float4*)xs[k])[h * 16 + d4];
                acc[k] += xv.x*ax + xv.y*ay + xv.z*az + xv.w*aw;
            }
        }
#pragma unroll
        for (int k = 0; k < NB; k++)
            poly[k][t] = acc[k] * acc[k] * 0.25f;   // /sqrt(P=16)
    }
    __syncthreads();

    // ---------- Phase 3: batch-split PRF + interleaved 512B store bursts ----------
    {
        const int r  = t >> 7;
        const int h  = (t >> 3) & 15;
        const int m4 = t & 7;
        const float sr = r ? s1 : s0;
        const float cr = r ? c1 : c0;
        const float er = r ? e1 : e0;
        const float4* og = (const float4*)omega + (size_t)((r * 16 + h) * 64) * 8 + m4;
        const size_t obase = r * 8192 + h * 512 + m4 * 4;

        // ---- Batch A: rows 0..3 accumulate ----
        float4 prA[4];
        {
            float4 acc[4];
#pragma unroll
            for (int k = 0; k < 4; k++) acc[k] = make_float4(0.f, 0.f, 0.f, 0.f);
#pragma unroll 4
            for (int d4 = 0; d4 < 16; d4++) {
                float4 o0 = og[(4 * d4 + 0) * 8];
                float4 o1 = og[(4 * d4 + 1) * 8];
                float4 o2 = og[(4 * d4 + 2) * 8];
                float4 o3 = og[(4 * d4 + 3) * 8];
#pragma unroll
                for (int k = 0; k < 4; k++) {
                    float4 xv = ((const float4*)xs[k])[h * 16 + d4];
                    acc[k].x += xv.x*o0.x; acc[k].y += xv.x*o0.y; acc[k].z += xv.x*o0.z; acc[k].w += xv.x*o0.w;
                    acc[k].x += xv.y*o1.x; acc[k].y += xv.y*o1.y; acc[k].z += xv.y*o1.z; acc[k].w += xv.y*o1.w;
                    acc[k].x += xv.z*o2.x; acc[k].y += xv.z*o2.y; acc[k].z += xv.z*o2.z; acc[k].w += xv.z*o2.w;
                    acc[k].x += xv.w*o3.x; acc[k].y += xv.w*o3.y; acc[k].z += xv.w*o3.z; acc[k].w += xv.w*o3.w;
                }
            }
#pragma unroll
            for (int k = 0; k < 4; k++) {
                float4 a = acc[k];
                prA[k].x = er * __expf(fminf(fmaxf(a.x * cr - sr, -20.f), 20.f));
                prA[k].y = er * __expf(fminf(fmaxf(a.y * cr - sr, -20.f), 20.f));
                prA[k].z = er * __expf(fminf(fmaxf(a.z * cr - sr, -20.f), 20.f));
                prA[k].w = er * __expf(fminf(fmaxf(a.w * cr - sr, -20.f), 20.f));
            }
        }

        // ---- Batch B: rows 4..7 accumulate, A's stores interleaved (4/iter) ----
        {
            float4 acc[4];
#pragma unroll
            for (int k = 0; k < 4; k++) acc[k] = make_float4(0.f, 0.f, 0.f, 0.f);
#pragma unroll
            for (int d4 = 0; d4 < 16; d4++) {
                float4 o0 = og[(4 * d4 + 0) * 8];
                float4 o1 = og[(4 * d4 + 1) * 8];
                float4 o2 = og[(4 * d4 + 2) * 8];
                float4 o3 = og[(4 * d4 + 3) * 8];
#pragma unroll
                for (int k = 0; k < 4; k++) {
                    float4 xv = ((const float4*)xs[4 + k])[h * 16 + d4];
                    acc[k].x += xv.x*o0.x; acc[k].y += xv.x*o0.y; acc[k].z += xv.x*o0.z; acc[k].w += xv.x*o0.w;
                    acc[k].x += xv.y*o1.x; acc[k].y += xv.y*o1.y; acc[k].z += xv.y*o1.z; acc[k].w += xv.y*o1.w;
                    acc[k].x += xv.z*o2.x; acc[k].y += xv.z*o2.y; acc[k].z += xv.z*o2.z; acc[k].w += xv.z*o2.w;
                    acc[k].x += xv.w*o3.x; acc[k].y += xv.w*o3.y; acc[k].z += xv.w*o3.z; acc[k].w += xv.w*o3.w;
                }
                // interleave 4 of batch A's 64 stores: row = d4&3, p-group = d4>>2 (512B burst)
                {
                    const int k  = d4 & 3;
                    const int p0 = (d4 >> 2) * 4;
                    float* ob = out + (size_t)(b0 + k) * 16384 + obase;
                    const float* pl = &poly[k][h * 16];
                    float4 pa = prA[k];
#pragma unroll
                    for (int pp = 0; pp < 4; pp++) {
                        float pf = pl[p0 + pp];
                        float4 o;
                        o.x = pf * pa.x; o.y = pf * pa.y; o.z = pf * pa.z; o.w = pf * pa.w;
                        __stcs((float4*)(ob + (p0 + pp) * 32), o);
                    }
                }
            }
            // exp + store batch B
#pragma unroll
            for (int k = 0; k < 4; k++) {
                float4 a = acc[k];
                float4 pr;
                pr.x = er * __expf(fminf(fmaxf(a.x * cr - sr, -20.f), 20.f));
                pr.y = er * __expf(fminf(fmaxf(a.y * cr - sr, -20.f), 20.f));
                pr.z = er * __expf(fminf(fmaxf(a.z * cr - sr, -20.f), 20.f));
                pr.w = er * __expf(fminf(fmaxf(a.w * cr - sr, -20.f), 20.f));

                float* ob = out + (size_t)(b0 + 4 + k) * 16384 + obase;
                const float* pl = &poly[4 + k][h * 16];
#pragma unroll
                for (int p = 0; p < 16; p++) {
                    float pf = pl[p];
                    float4 o;
                    o.x = pf * pr.x; o.y = pf * pr.y; o.z = pf * pr.z; o.w = pf * pr.w;
                    __stcs((float4*)(ob + p * 32), o);
                }
            }
        }
    }
}

extern "C" void kernel_launch(void* const* d_in, const int* in_sizes, int n_in,
                              void* d_out, int out_size) {
    const float* x       = (const float*)d_in[0];
    const float* omega   = (const float*)d_in[1];
    const float* anchors = (const float*)d_in[2];
    float* out = (float*)d_out;

    const double C   = 2.0 + 1e-6;
    const double rt2 = 1.4142135623730951;
    const double n0d = 2.0 - rt2, n1d = 2.0 + rt2;
    const double w0d = (2.0 + rt2) / 4.0, w1d = (2.0 - rt2) / 4.0;

    float s0 = (float)(n0d / C);
    float s1 = (float)(n1d / C);
    float c0 = sqrtf(2.0f * s0);
    float c1 = sqrtf(2.0f * s1);
    float invSqrtM = 1.0f / sqrtf(32.0f);
    float e0 = sqrtf((float)(w0d / C)) * invSqrtM;
    float e1 = sqrtf((float)(w1d / C)) * invSqrtM;

    slay_kernel<<<8192 / NB, THREADS>>>(x, omega, anchors, out,
                                        s0, s1, c0, c1, e0, e1);
    (void)in_sizes; (void)n_in; (void)out_size;
}